// round 17
// baseline (speedup 1.0000x reference)
#include <cuda_runtime.h>
#include <cuda_fp16.h>

// ---------------------------------------------------------------------------
// AdaUp, fp16 mma.sync + cp.async. Fused pipeline:
//   s2: k0w -> k0t-low  ||  s0: k0t-high -> (wait k0w) k1f ; join -> k2f -> k4
//   K2f: GEMM + overlapped t/W2 staging at kt=3 + fragment epilogue + q-GEMM
//   K4 : 32-thread uint4 offset-stencil gather -> 4-pt deformable sample
// ---------------------------------------------------------------------------

#define NB    8
#define HWLO  4096
#define HWHI  16384

__device__ __half g_h16[(size_t)NB * HWLO * 256];
__device__ __half g_l16[(size_t)NB * HWHI * 256];
__device__ __half g_wh[1024 * 256];
__device__ __half g_t16[(size_t)NB * HWLO * 256];
__device__ __half g_proc16[(size_t)NB * HWLO * 256];
__device__ __half g_q16h[2][(size_t)NB * HWHI * 72];

__device__ __forceinline__ unsigned smem_u32(const void* p) {
    unsigned a;
    asm("{ .reg .u64 t; cvta.to.shared.u64 t, %1; cvt.u32.u64 %0, t; }" : "=r"(a) : "l"(p));
    return a;
}
__device__ __forceinline__ unsigned sw128(unsigned o) { return o ^ ((o >> 3) & 0x70); }
__device__ __forceinline__ unsigned pack_h2(float lo, float hi) {
    unsigned u;
    asm("cvt.rn.f16x2.f32 %0, %1, %2;" : "=r"(u) : "f"(hi), "f"(lo));
    return u;
}
__device__ __forceinline__ void cpa16(unsigned dst, const void* src) {
    asm volatile("cp.async.cg.shared.global [%0], [%1], 16;" :: "r"(dst), "l"(src));
}
#define CP_COMMIT() asm volatile("cp.async.commit_group;" ::: "memory")
template <int N> __device__ __forceinline__ void cp_wait() {
    asm volatile("cp.async.wait_group %0;" :: "n"(N) : "memory");
}

#define LDSM_X4(r0, r1, r2, r3, addr) \
    asm volatile("ldmatrix.sync.aligned.m8n8.x4.shared.b16 {%0,%1,%2,%3}, [%4];" \
                 : "=r"(r0), "=r"(r1), "=r"(r2), "=r"(r3) : "r"(addr))
#define LDSM_X2(r0, r1, addr) \
    asm volatile("ldmatrix.sync.aligned.m8n8.x2.shared.b16 {%0,%1}, [%2];" \
                 : "=r"(r0), "=r"(r1) : "r"(addr))
#define MMA_F16(d, a, b) \
    asm volatile("mma.sync.aligned.m16n8k16.row.col.f32.f16.f16.f32 " \
                 "{%0,%1,%2,%3}, {%4,%5,%6,%7}, {%8,%9}, {%0,%1,%2,%3};" \
                 : "+f"((d)[0]), "+f"((d)[1]), "+f"((d)[2]), "+f"((d)[3]) \
                 : "r"((a)[0]), "r"((a)[1]), "r"((a)[2]), "r"((a)[3]), \
                   "r"((b)[0]), "r"((b)[1]))

__device__ __forceinline__ float2 h2f(unsigned u) {
    return __half22float2(*(const __half2*)&u);
}

// ===========================================================================
// K0t: [b][k][s] f32 -> [b][s][k] fp16
// ===========================================================================
__global__ __launch_bounds__(256)
void k0t(const float* __restrict__ src, int which, int S)
{
    __shared__ float ts[64][65];
    __half* dst = which ? g_l16 : g_h16;
    const int tid = threadIdx.x;
    const int s0 = blockIdx.x * 64, k0 = blockIdx.y * 64, b = blockIdx.z;
    const float* in = src + (size_t)b * 256 * S + (size_t)k0 * S + s0;
#pragma unroll
    for (int i = 0; i < 16; ++i) {
        const int idx = i * 256 + tid;
        const int kk = idx >> 6, ss = idx & 63;
        ts[ss][kk] = in[(size_t)kk * S + ss];
    }
    __syncthreads();
    unsigned* ob = (unsigned*)(dst + ((size_t)b * S + s0) * 256 + k0);
#pragma unroll
    for (int i = 0; i < 8; ++i) {
        const int idx = i * 256 + tid;
        const int ss = idx >> 5, kp = (idx & 31) * 2;
        ob[(size_t)ss * 128 + (kp >> 1)] = pack_h2(ts[ss][kp], ts[ss][kp + 1]);
    }
}

// ===========================================================================
// K0w: pack weights fp16 [row][256]
// ===========================================================================
__global__ __launch_bounds__(256)
void k0w(const float* __restrict__ W1, const float* __restrict__ Wf,
         const float* __restrict__ W2)
{
    const int row = blockIdx.x, c = threadIdx.x;
    float v = 0.f;
    if (row < 256)      v = W1[(size_t)row * 512 + c];
    else if (row < 512) v = Wf[(size_t)(row - 256) * 256 + c];
    else if (row < 768) v = W1[(size_t)(row - 512) * 512 + 256 + c];
    else if (row < 840) {
        const int t = (row - 768) >> 3, o = (row - 768) & 7;
        v = W2[(size_t)o * 2304 + c * 9 + t];
    }
    g_wh[(size_t)row * 256 + c] = __float2half(v);
}

// ===========================================================================
// cp.async one 64-k A chunk (128 rows x 128 bytes)
// ===========================================================================
__device__ __forceinline__ void load_A_chunk(unsigned bufA, const __half* A16,
                                             int kt, int tid)
{
    const int row = tid >> 1, c4 = (tid & 1) * 4;
#pragma unroll
    for (int j = 0; j < 4; ++j) {
        const int c = c4 + j;
        cpa16(bufA + sw128(row * 128 + c * 16), A16 + (size_t)row * 256 + kt * 64 + c * 8);
    }
}

// ===========================================================================
// K1f: [t | proc] = [W1a | Wf] @ high ; grid (256, 4)
// ===========================================================================
__global__ __launch_bounds__(256, 2)
void k1f(const float* __restrict__ bf)
{
    extern __shared__ char dsm[];
    const unsigned sb = smem_u32(dsm), sbB = sb + 32768;
    const int tid = threadIdx.x, lane = tid & 31, warp = tid >> 5;
    const int wm = warp & 1, wn = warp >> 1;
    const int m0 = blockIdx.x * 128;
    const int ny = blockIdx.y >> 1, nhalf = blockIdx.y & 1;
    const int bb = m0 >> 12, s0 = m0 & 4095;
    const int brow0 = ny * 256 + nhalf * 128;

    const __half* A16 = g_h16 + ((size_t)bb * HWLO + s0) * 256;

    unsigned aoff[4], boff[2];
#pragma unroll
    for (int mt = 0; mt < 4; ++mt)
        aoff[mt] = ((unsigned)(wm * 64 + mt * 16 + (lane & 15)) << 7) + (lane >> 4) * 16;
#pragma unroll
    for (int p = 0; p < 2; ++p)
        boff[p] = ((unsigned)(wn * 32 + p * 16 + (lane & 7) + ((lane >> 4) & 1) * 8) << 7)
                  + ((lane >> 3) & 1) * 16;

    float d[4][4][4];
#pragma unroll
    for (int i = 0; i < 4; ++i)
#pragma unroll
        for (int j = 0; j < 4; ++j)
#pragma unroll
            for (int e = 0; e < 4; ++e) d[i][j][e] = 0.f;

#pragma unroll
    for (int i = 0; i < 16; ++i) {
        const int idx = i * 256 + tid;
        const int n = idx >> 5, c = idx & 31;
        cpa16(sbB + (c >> 3) * 16384 + sw128(n * 128 + (c & 7) * 16),
              g_wh + (size_t)(brow0 + n) * 256 + c * 8);
    }
    load_A_chunk(sb, A16, 0, tid);
    CP_COMMIT();
    load_A_chunk(sb + 16384, A16, 1, tid);
    CP_COMMIT();

    for (int kt = 0; kt < 4; ++kt) {
        if (kt < 3) cp_wait<1>(); else cp_wait<0>();
        __syncthreads();
        const unsigned bufA = sb + (kt & 1) * 16384;
        const unsigned bufB = sbB + kt * 16384;
#pragma unroll
        for (int ks = 0; ks < 4; ++ks) {
            const unsigned ksb = ks * 32;
            unsigned a[4][4], b[4][2];
#pragma unroll
            for (int mt = 0; mt < 4; ++mt)
                LDSM_X4(a[mt][0], a[mt][1], a[mt][2], a[mt][3], bufA + sw128(aoff[mt] + ksb));
            LDSM_X4(b[0][0], b[0][1], b[1][0], b[1][1], bufB + sw128(boff[0] + ksb));
            LDSM_X4(b[2][0], b[2][1], b[3][0], b[3][1], bufB + sw128(boff[1] + ksb));
#pragma unroll
            for (int mt = 0; mt < 4; ++mt)
#pragma unroll
                for (int nt = 0; nt < 4; ++nt)
                    MMA_F16(d[mt][nt], a[mt], b[nt]);
        }
        __syncthreads();
        if (kt < 2) { load_A_chunk(sb + (kt & 1) * 16384, A16, kt + 2, tid); CP_COMMIT(); }
    }

#pragma unroll
    for (int mt = 0; mt < 4; ++mt) {
        const int row = m0 + wm * 64 + mt * 16 + (lane >> 2);
#pragma unroll
        for (int nt = 0; nt < 4; ++nt) {
            const int col = nhalf * 128 + wn * 32 + nt * 8 + (lane & 3) * 2;
            if (ny == 0) {
                *(unsigned*)&g_t16[(size_t)row * 256 + col] =
                    pack_h2(d[mt][nt][0], d[mt][nt][1]);
                *(unsigned*)&g_t16[(size_t)(row + 8) * 256 + col] =
                    pack_h2(d[mt][nt][2], d[mt][nt][3]);
            } else {
                const float b0 = bf[col], b1 = bf[col + 1];
                *(unsigned*)&g_proc16[(size_t)row * 256 + col] =
                    pack_h2(d[mt][nt][0] + b0, d[mt][nt][1] + b1);
                *(unsigned*)&g_proc16[(size_t)(row + 8) * 256 + col] =
                    pack_h2(d[mt][nt][2] + b0, d[mt][nt][3] + b1);
            }
        }
    }
}

// ===========================================================================
// K2f: GEMM W1b@low -> fragment-direct epilogue -> in-CTA q-GEMM.
// ===========================================================================
__global__ __launch_bounds__(256, 2)
void k2f(const float* __restrict__ b1)
{
    extern __shared__ char dsm[];
    const unsigned sb = smem_u32(dsm), sbB = sb + 32768;
    const int tid = threadIdx.x, lane = tid & 31, warp = tid >> 5;
    const int wm = warp & 1, wn = warp >> 1;
    const int m0 = blockIdx.x * 128;
    const int n0 = blockIdx.y * 128;
    const int bb = m0 >> 14, s0 = m0 & 16383;
    const int brow0 = 512 + n0;

    const __half* A16 = g_l16 + ((size_t)bb * HWHI + s0) * 256;

    const int yy = s0 >> 7;
    int jy0_, jy1_;
    float wy0, wy1;
    if (yy & 1) { jy0_ = yy >> 1; jy1_ = ((yy >> 1) + 1 > 63) ? 63 : (yy >> 1) + 1; wy0 = 0.75f; wy1 = 0.25f; }
    else        { jy0_ = ((yy >> 1) - 1 < 0) ? 0 : (yy >> 1) - 1; jy1_ = yy >> 1;   wy0 = 0.25f; wy1 = 0.75f; }

    unsigned aoff[4], boff[2];
#pragma unroll
    for (int mt = 0; mt < 4; ++mt)
        aoff[mt] = ((unsigned)(wm * 64 + mt * 16 + (lane & 15)) << 7) + (lane >> 4) * 16;
#pragma unroll
    for (int p = 0; p < 2; ++p)
        boff[p] = ((unsigned)(wn * 32 + p * 16 + (lane & 7) + ((lane >> 4) & 1) * 8) << 7)
                  + ((lane >> 3) & 1) * 16;

    float d[4][4][4];
#pragma unroll
    for (int i = 0; i < 4; ++i)
#pragma unroll
        for (int j = 0; j < 4; ++j)
#pragma unroll
            for (int e = 0; e < 4; ++e) d[i][j][e] = 0.f;

#pragma unroll
    for (int i = 0; i < 16; ++i) {
        const int idx = i * 256 + tid;
        const int n = idx >> 5, c = idx & 31;
        cpa16(sbB + (c >> 3) * 16384 + sw128(n * 128 + (c & 7) * 16),
              g_wh + (size_t)(brow0 + n) * 256 + c * 8);
    }
    load_A_chunk(sb, A16, 0, tid);
    CP_COMMIT();
    load_A_chunk(sb + 16384, A16, 1, tid);
    CP_COMMIT();

    for (int kt = 0; kt < 4; ++kt) {
        if (kt < 3) cp_wait<1>(); else cp_wait<0>();
        __syncthreads();
        if (kt == 3) {
            const __half* tb = g_t16 + (size_t)bb * HWLO * 256;
#pragma unroll
            for (int r = 0; r < 2; ++r) {
                const int jy = r ? jy1_ : jy0_;
                const unsigned dstb = r ? 49152u : 0u;
#pragma unroll
                for (int i = 0; i < 4; ++i) {
                    const int idx = i * 256 + tid;
                    const int j = idx >> 4, cc = idx & 15;
                    cpa16(sb + dstb + idx * 16,
                          tb + (size_t)(jy * 64 + j) * 256 + n0 + cc * 8);
                }
            }
#pragma unroll
            for (int i = 0; i < 3; ++i) {
                const int idx = i * 256 + tid;
                if (idx < 640) {
                    const int n = idx >> 3, c8 = idx & 7;
                    cpa16(sb + 65536 + sw128(n * 128 + c8 * 16),
                          g_wh + (size_t)(768 + n) * 256 + n0 + c8 * 8);
                }
            }
            CP_COMMIT();
        }
        const unsigned bufA = sb + (kt & 1) * 16384;
        const unsigned bufB = sbB + kt * 16384;
#pragma unroll
        for (int ks = 0; ks < 4; ++ks) {
            const unsigned ksb = ks * 32;
            unsigned a[4][4], b[4][2];
#pragma unroll
            for (int mt = 0; mt < 4; ++mt)
                LDSM_X4(a[mt][0], a[mt][1], a[mt][2], a[mt][3], bufA + sw128(aoff[mt] + ksb));
            LDSM_X4(b[0][0], b[0][1], b[1][0], b[1][1], bufB + sw128(boff[0] + ksb));
            LDSM_X4(b[2][0], b[2][1], b[3][0], b[3][1], bufB + sw128(boff[1] + ksb));
#pragma unroll
            for (int mt = 0; mt < 4; ++mt)
#pragma unroll
                for (int nt = 0; nt < 4; ++nt)
                    MMA_F16(d[mt][nt], a[mt], b[nt]);
        }
        __syncthreads();
        if (kt < 2) { load_A_chunk(sb + (kt & 1) * 16384, A16, kt + 2, tid); CP_COMMIT(); }
    }

#pragma unroll
    for (int i = 0; i < 3; ++i) {
        const int idx = i * 256 + tid;
        if (idx < 640) {
            const int n = idx >> 3, c8 = idx & 7;
            cpa16(sb + 81920 + sw128(n * 128 + c8 * 16),
                  g_wh + (size_t)(768 + n) * 256 + n0 + 64 + c8 * 8);
        }
    }
    CP_COMMIT();
    cp_wait<1>();
    __syncthreads();

    const __half* r0p = (const __half*)dsm;
    const __half* r1p = (const __half*)(dsm + 49152);
#pragma unroll
    for (int mt = 0; mt < 4; ++mt) {
#pragma unroll
        for (int h = 0; h < 2; ++h) {
            const int r = wm * 64 + mt * 16 + (lane >> 2) + h * 8;
            const int tw = r >> 1;
            int jx0, jx1;
            float wx0, wx1;
            if (r & 1) { jx0 = tw; jx1 = (tw + 1 > 63) ? 63 : tw + 1; wx0 = 0.75f; wx1 = 0.25f; }
            else       { jx0 = (tw - 1 < 0) ? 0 : tw - 1; jx1 = tw;   wx0 = 0.25f; wx1 = 0.75f; }
            const float wa = wy0 * wx0, wb_ = wy0 * wx1, wc = wy1 * wx0, wd = wy1 * wx1;
#pragma unroll
            for (int nt = 0; nt < 4; ++nt) {
                const int col = wn * 32 + nt * 8 + (lane & 3) * 2;
                float2 bv = *(const float2*)&b1[n0 + col];
                float2 f00 = h2f(*(const unsigned*)&r0p[jx0 * 128 + col]);
                float2 f01 = h2f(*(const unsigned*)&r0p[jx1 * 128 + col]);
                float2 f10 = h2f(*(const unsigned*)&r1p[jx0 * 128 + col]);
                float2 f11 = h2f(*(const unsigned*)&r1p[jx1 * 128 + col]);
                float o0 = fmaxf(d[mt][nt][h * 2 + 0] + bv.x +
                                 wa * f00.x + wb_ * f01.x + wc * f10.x + wd * f11.x, 0.f);
                float o1 = fmaxf(d[mt][nt][h * 2 + 1] + bv.y +
                                 wa * f00.y + wb_ * f01.y + wc * f10.y + wd * f11.y, 0.f);
                *(unsigned*)(dsm + (col < 64 ? 32768u : 16384u) +
                             sw128((unsigned)r * 128 + (col & 63) * 2)) = pack_h2(o0, o1);
            }
        }
    }
    cp_wait<0>();
    __syncthreads();

    const int wm2 = warp >> 1, wn2 = warp & 1;
    unsigned aoff2[2], boffp2[2], boffs2;
#pragma unroll
    for (int mt = 0; mt < 2; ++mt)
        aoff2[mt] = ((unsigned)(wm2 * 32 + mt * 16 + (lane & 15)) << 7) + (lane >> 4) * 16;
#pragma unroll
    for (int p = 0; p < 2; ++p)
        boffp2[p] = ((unsigned)(wn2 * 40 + p * 16 + (lane & 7) + ((lane >> 4) & 1) * 8) << 7)
                    + ((lane >> 3) & 1) * 16;
    boffs2 = ((unsigned)(wn2 * 40 + 32 + (lane & 7)) << 7) + ((lane >> 3) & 1) * 16;

    float dq[2][5][4];
#pragma unroll
    for (int i = 0; i < 2; ++i)
#pragma unroll
        for (int j = 0; j < 5; ++j)
#pragma unroll
            for (int e = 0; e < 4; ++e) dq[i][j][e] = 0.f;

    const unsigned qa_base[2] = {32768u, 16384u};
    const unsigned qb_base[2] = {65536u, 81920u};
#pragma unroll
    for (int ck = 0; ck < 2; ++ck) {
        const unsigned bufA = sb + qa_base[ck];
        const unsigned bufB = sb + qb_base[ck];
#pragma unroll
        for (int ks = 0; ks < 4; ++ks) {
            const unsigned ksb = ks * 32;
            unsigned a[2][4], b[5][2];
#pragma unroll
            for (int mt = 0; mt < 2; ++mt)
                LDSM_X4(a[mt][0], a[mt][1], a[mt][2], a[mt][3], bufA + sw128(aoff2[mt] + ksb));
            LDSM_X4(b[0][0], b[0][1], b[1][0], b[1][1], bufB + sw128(boffp2[0] + ksb));
            LDSM_X4(b[2][0], b[2][1], b[3][0], b[3][1], bufB + sw128(boffp2[1] + ksb));
            LDSM_X2(b[4][0], b[4][1], bufB + sw128(boffs2 + ksb));
#pragma unroll
            for (int mt = 0; mt < 2; ++mt)
#pragma unroll
                for (int nt = 0; nt < 5; ++nt)
                    MMA_F16(dq[mt][nt], a[mt], b[nt]);
        }
    }

    __half* gq = g_q16h[blockIdx.y];
#pragma unroll
    for (int mt = 0; mt < 2; ++mt) {
        const int row = m0 + wm2 * 32 + mt * 16 + (lane >> 2);
#pragma unroll
        for (int nt = 0; nt < 5; ++nt) {
            const int col = wn2 * 40 + nt * 8 + (lane & 3) * 2;
            if (col < 72) {
                *(unsigned*)&gq[(size_t)row * 72 + col] = pack_h2(dq[mt][nt][0], dq[mt][nt][1]);
                *(unsigned*)&gq[(size_t)(row + 8) * 72 + col] = pack_h2(dq[mt][nt][2], dq[mt][nt][3]);
            }
        }
    }
}

// ===========================================================================
// K4: phase A = 32 pixel-threads gather uint4 taps (8 ch at once, both halves),
//     combine via smem, then 4-pt deformable bilinear sample (uint4 taps).
// ===========================================================================
__global__ __launch_bounds__(256)
void k4_sample(const float* __restrict__ b2, float* __restrict__ out)
{
    __shared__ int   sh_idx[32][16];
    __shared__ float sh_w[32][16];
    __shared__ float sh_off[32][8];
    __shared__ float sh_t[32 * 289 + 8];

    const int tid = threadIdx.x;
    const int xt = blockIdx.x;
    const int y  = blockIdx.y;
    const int bb = blockIdx.z;
    const int x0 = xt * 32;

    // phase A1: thread = pixel; 9 taps x 2 halves, one uint4 (8 ch) each
    if (tid < 32) {
        const int x = x0 + tid;
        float acc[8];
#pragma unroll
        for (int j = 0; j < 8; ++j) acc[j] = 0.f;
        const __half* q0 = g_q16h[0] + (size_t)bb * HWHI * 72;
        const __half* q1 = g_q16h[1] + (size_t)bb * HWHI * 72;
#pragma unroll
        for (int dy = 0; dy < 3; ++dy) {
            const int yyt = y + dy - 1;
            if (yyt < 0 || yyt > 127) continue;
#pragma unroll
            for (int dx = 0; dx < 3; ++dx) {
                const int xxt = x + dx - 1;
                if (xxt < 0 || xxt > 127) continue;
                const size_t qi = (size_t)(yyt * 128 + xxt) * 72 + (dy * 3 + dx) * 8;
                const uint4 u0 = *(const uint4*)&q0[qi];
                const uint4 u1 = *(const uint4*)&q1[qi];
                float2 a0 = h2f(u0.x), a1 = h2f(u0.y), a2 = h2f(u0.z), a3 = h2f(u0.w);
                float2 c0 = h2f(u1.x), c1 = h2f(u1.y), c2 = h2f(u1.z), c3 = h2f(u1.w);
                acc[0] += a0.x + c0.x; acc[1] += a0.y + c0.y;
                acc[2] += a1.x + c1.x; acc[3] += a1.y + c1.y;
                acc[4] += a2.x + c2.x; acc[5] += a2.y + c2.y;
                acc[6] += a3.x + c3.x; acc[7] += a3.y + c3.y;
            }
        }
#pragma unroll
        for (int j = 0; j < 8; ++j) sh_off[tid][j] = acc[j];
    }
    __syncthreads();

    if (tid < 128) {
        const int px = tid >> 2, p = tid & 3;
        const int x = x0 + px;
        const float ax = sh_off[px][2 * p]     + b2[2 * p];
        const float ay = sh_off[px][2 * p + 1] + b2[2 * p + 1];
        const float ox = ax * (1.0f / 64.0f);
        const float oy = ay * (1.0f / 64.0f);
        const float gx = fmaf((float)x, 2.0f / 127.0f, -1.0f) + ox;
        const float gy = fmaf((float)y, 2.0f / 127.0f, -1.0f) + oy;
        const float gxp = fminf(fmaxf(fmaf(gx, 32.0f, 31.5f), 0.0f), 63.0f);
        const float gyp = fminf(fmaxf(fmaf(gy, 32.0f, 31.5f), 0.0f), 63.0f);
        const float fx0 = floorf(gxp), fy0 = floorf(gyp);
        const int ix0 = (int)fx0, iy0 = (int)fy0;
        const float fx = gxp - fx0, fy = gyp - fy0;
        const int ix1 = (ix0 + 1 > 63) ? 63 : ix0 + 1;
        const int iy1 = (iy0 + 1 > 63) ? 63 : iy0 + 1;
        const int q = p * 4;
        sh_idx[px][q + 0] = (iy0 * 64 + ix0) * 32;
        sh_idx[px][q + 1] = (iy0 * 64 + ix1) * 32;
        sh_idx[px][q + 2] = (iy1 * 64 + ix0) * 32;
        sh_idx[px][q + 3] = (iy1 * 64 + ix1) * 32;
        sh_w[px][q + 0] = (1.f - fx) * (1.f - fy) * 0.25f;
        sh_w[px][q + 1] = fx * (1.f - fy) * 0.25f;
        sh_w[px][q + 2] = (1.f - fx) * fy * 0.25f;
        sh_w[px][q + 3] = fx * fy * 0.25f;
    }
    __syncthreads();

    const int lane = tid & 31, wrp = tid >> 5;
    const uint4* pb = (const uint4*)(g_proc16 + (size_t)bb * HWLO * 256) + lane;

#pragma unroll
    for (int r = 0; r < 4; ++r) {
        const int px = wrp * 4 + r;
        float acc[8];
#pragma unroll
        for (int j = 0; j < 8; ++j) acc[j] = 0.f;
#pragma unroll
        for (int t = 0; t < 16; ++t) {
            const float wt = sh_w[px][t];
            const uint4 u = pb[sh_idx[px][t]];
            float2 f0 = h2f(u.x), f1 = h2f(u.y), f2 = h2f(u.z), f3 = h2f(u.w);
            acc[0] = fmaf(wt, f0.x, acc[0]); acc[1] = fmaf(wt, f0.y, acc[1]);
            acc[2] = fmaf(wt, f1.x, acc[2]); acc[3] = fmaf(wt, f1.y, acc[3]);
            acc[4] = fmaf(wt, f2.x, acc[4]); acc[5] = fmaf(wt, f2.y, acc[5]);
            acc[6] = fmaf(wt, f3.x, acc[6]); acc[7] = fmaf(wt, f3.y, acc[7]);
        }
        float* dstp = &sh_t[px * 289 + lane * 9];
#pragma unroll
        for (int j = 0; j < 8; ++j) dstp[j] = acc[j];
    }
    __syncthreads();

    const int xl = tid & 31;
    const int c0 = tid >> 5;
#pragma unroll
    for (int i = 0; i < 32; ++i) {
        const int c = c0 * 32 + i;
        out[((size_t)bb * 256 + c) * HWHI + y * 128 + x0 + xl] =
            sh_t[xl * 289 + (c >> 3) * 9 + (c & 7)];
    }
}

// ===========================================================================
extern "C" void kernel_launch(void* const* d_in, const int* in_sizes, int n_in,
                              void* d_out, int out_size)
{
    const float* high = (const float*)d_in[0];
    const float* low  = (const float*)d_in[1];
    const float* W1   = (const float*)d_in[2];
    const float* b1   = (const float*)d_in[3];
    const float* W2   = (const float*)d_in[4];
    const float* b2   = (const float*)d_in[5];
    const float* Wf   = (const float*)d_in[6];
    const float* bf   = (const float*)d_in[7];
    float* out = (float*)d_out;

    const int SM_K1 = 98304;
    const int SM_K2 = 98304;

    static cudaStream_t s2;
    static cudaEvent_t e_fork, e_w, e_join;
    static int inited = 0;
    if (!inited) {
        cudaFuncSetAttribute(k1f, cudaFuncAttributeMaxDynamicSharedMemorySize, SM_K1);
        cudaFuncSetAttribute(k2f, cudaFuncAttributeMaxDynamicSharedMemorySize, SM_K2);
        cudaStreamCreateWithFlags(&s2, cudaStreamNonBlocking);
        cudaEventCreateWithFlags(&e_fork, cudaEventDisableTiming);
        cudaEventCreateWithFlags(&e_w, cudaEventDisableTiming);
        cudaEventCreateWithFlags(&e_join, cudaEventDisableTiming);
        inited = 1;
    }

    cudaEventRecord(e_fork, 0);
    cudaStreamWaitEvent(s2, e_fork, 0);
    k0w<<<848, 256, 0, s2>>>(W1, Wf, W2);
    cudaEventRecord(e_w, s2);
    k0t<<<dim3(256, 4, 8), 256, 0, s2>>>(low, 1, HWHI);
    cudaEventRecord(e_join, s2);

    k0t<<<dim3(64, 4, 8), 256>>>(high, 0, HWLO);
    cudaStreamWaitEvent(0, e_w, 0);
    k1f<<<dim3(256, 4), 256, SM_K1>>>(bf);

    cudaStreamWaitEvent(0, e_join, 0);
    k2f<<<dim3(1024, 2), 256, SM_K2>>>(b1);
    k4_sample<<<dim3(4, 128, 8), 256>>>(b2, out);
}